// round 12
// baseline (speedup 1.0000x reference)
#include <cuda_runtime.h>
#include <cuda_bf16.h>
#include <cstdint>

// ---------------- hash-grid constants (precomputed from reference config) ----
__constant__ float c_scale[16] = {
    15.0f,          21.1106061f,   29.5549331f,   41.2242532f,
    57.3502375f,    79.6349472f,  110.4304720f,  152.9872000f,
    211.7969070f,  293.0667790f,  405.3746690f,  560.5743900f,
    775.0469010f, 1071.4291820f, 1481.0036600f, 2047.0f
};
__constant__ uint32_t c_res1[5] = {17u, 24u, 32u, 44u, 60u};
__constant__ int c_offset[16] = {
    0, 4920, 18744, 51512, 136696, 352696, 876984, 1401272,
    1925560, 2449848, 2974136, 3498424, 4022712, 4547000, 5071288, 5595576
};

// W chunk stream: 12 chunks (L1 c0..3, L2 c0..3, L3 c0..3), flat smem images
// (rows = K, 64 cols + 8 pad, stride 72 bf16 = 144 B).
__constant__ uint32_t c_chunk_off[12] = {
    0u, 4608u, 9216u, 13824u,
    18432u, 55296u, 92160u, 129024u,
    165888u, 202752u, 239616u, 276480u
};
__constant__ uint32_t c_chunk_bytes[12] = {
    4608u, 4608u, 4608u, 4608u,
    36864u, 36864u, 36864u, 36864u,
    36864u, 36864u, 36864u, 36864u
};

#define NPTS 524288
#define THREADS 384
#define ROWS 192

// pre-baked weight chunk blob (allocation-free rule: __device__ global)
__device__ char g_wblob[313344];

// ------------------------------------------------------- weight baking ------
__global__ void cvtw_kernel(const float* __restrict__ w1,
                            const float* __restrict__ w2,
                            const float* __restrict__ w3,
                            char* __restrict__ blob) {
    int i = blockIdx.x * 256 + threadIdx.x;   // i = k*256 + n, 65536 total
    int k = i >> 8, n = i & 255;
    uint32_t nc = (uint32_t)(n >> 6);
    uint32_t eoff = ((uint32_t)k * 72u + (uint32_t)(n & 63)) * 2u;
    *(__nv_bfloat16*)(blob + 18432u + nc * 36864u + eoff) = __float2bfloat16(w2[i]);
    *(__nv_bfloat16*)(blob + 165888u + nc * 36864u + eoff) = __float2bfloat16(w3[i]);
    if (k < 32)
        *(__nv_bfloat16*)(blob + nc * 4608u + eoff) = __float2bfloat16(w1[i]);
}

// ------------------------------------------------------------ PTX helpers ---
__device__ __forceinline__ uint32_t scvta(const void* p) {
    return (uint32_t)__cvta_generic_to_shared(p);
}
__device__ __forceinline__ void ldsm_x4(uint32_t* r, uint32_t addr) {
    asm volatile("ldmatrix.sync.aligned.m8n8.x4.shared.b16 {%0,%1,%2,%3}, [%4];"
                 : "=r"(r[0]), "=r"(r[1]), "=r"(r[2]), "=r"(r[3]) : "r"(addr));
}
__device__ __forceinline__ void ldsm_x4_t(uint32_t* r, uint32_t addr) {
    asm volatile("ldmatrix.sync.aligned.m8n8.x4.trans.shared.b16 {%0,%1,%2,%3}, [%4];"
                 : "=r"(r[0]), "=r"(r[1]), "=r"(r[2]), "=r"(r[3]) : "r"(addr));
}
__device__ __forceinline__ void mma_bf16(float* c, const uint32_t* a, const uint32_t* b) {
    asm volatile("mma.sync.aligned.m16n8k16.row.col.f32.bf16.bf16.f32 "
                 "{%0,%1,%2,%3}, {%4,%5,%6,%7}, {%8,%9}, {%0,%1,%2,%3};"
                 : "+f"(c[0]), "+f"(c[1]), "+f"(c[2]), "+f"(c[3])
                 : "r"(a[0]), "r"(a[1]), "r"(a[2]), "r"(a[3]),
                   "r"(b[0]), "r"(b[1]));
}
__device__ __forceinline__ void cp16(uint32_t smem, const void* gmem) {
    asm volatile("cp.async.cg.shared.global [%0], [%1], 16;"
                 :: "r"(smem), "l"(gmem));
}
__device__ __forceinline__ void cp_commit() {
    asm volatile("cp.async.commit_group;");
}
template <int NG>
__device__ __forceinline__ void cp_wait() {
    asm volatile("cp.async.wait_group %0;" :: "n"(NG));
}
__device__ __forceinline__ uint32_t packrelu(float a, float b) {
    __nv_bfloat162 t = __float22bfloat162_rn(
        make_float2(fmaxf(a, 0.0f), fmaxf(b, 0.0f)));
    return *(uint32_t*)&t;
}

// -------------------------------------------------------------- SMEM map ----
// 3-slot W ring (slot = s % 3). At chunk s, issuing s+2 targets slot (s+2)%3
// == (s-1)%3, which held chunk s-1 — finished by all warps before this
// iteration's barrier.
#define WSLOT     36864
#define W_OFF     0
#define ACT_OFF   (3 * WSLOT)                 // 110592 : 192 x 264 bf16 act
#define SA        264
#define SF        40                          // feat stride (colocated in act)
#define BIAS_OFF  (ACT_OFF + ROWS * SA * 2)   // 211968 : float[768] b1|b2|b3
#define W4_OFF    (BIAS_OFF + 768 * 4)        // 215040 : float[772] w4|b4
#define SMEM_BYTES (W4_OFF + 772 * 4)         // 218128

// issue cp.async for chunk s into slot s%3 (s compile-time in unrolled loops)
__device__ __forceinline__ void issue_chunk(uint32_t sb, const char* blob,
                                            int s, int tid) {
    uint32_t dst = sb + W_OFF + (uint32_t)(s % 3) * WSLOT;
    uint32_t off = c_chunk_off[s];
    uint32_t bytes = c_chunk_bytes[s];
    for (uint32_t o = (uint32_t)tid * 16u; o < bytes; o += THREADS * 16u)
        cp16(dst + o, blob + off + o);
    cp_commit();
}

// MMA over one W chunk (64 cols) with register A. acc[8][4] += A*W.
template <int KB>
__device__ __forceinline__ void chunk_mma(uint32_t sW, int lr2, int lc2,
                                          const uint32_t (*aF)[4],
                                          float (*acc)[4]) {
    #pragma unroll
    for (int kb = 0; kb < KB; kb++) {
        uint32_t bt[4][4];
        #pragma unroll
        for (int nq = 0; nq < 4; nq++)
            ldsm_x4_t(bt[nq], sW + (uint32_t)(((kb * 16 + lr2) * 72
                                               + nq * 16 + lc2) * 2));
        #pragma unroll
        for (int nq = 0; nq < 4; nq++) {
            mma_bf16(acc[2 * nq],     aF[kb], &bt[nq][0]);
            mma_bf16(acc[2 * nq + 1], aF[kb], &bt[nq][2]);
        }
    }
}

// MMA over one W chunk with A re-loaded from smem act buffer per kblock.
__device__ __forceinline__ void chunk_mma_smemA(uint32_t sW, uint32_t sAct,
                                                int m0, int lr2, int lc2,
                                                float (*acc)[4]) {
    #pragma unroll
    for (int kb = 0; kb < 16; kb++) {
        uint32_t aF[4];
        ldsm_x4(aF, sAct + (uint32_t)(((m0 + lr2) * SA + kb * 16 + lc2) * 2));
        uint32_t bt[4][4];
        #pragma unroll
        for (int nq = 0; nq < 4; nq++)
            ldsm_x4_t(bt[nq], sW + (uint32_t)(((kb * 16 + lr2) * 72
                                               + nq * 16 + lc2) * 2));
        #pragma unroll
        for (int nq = 0; nq < 4; nq++) {
            mma_bf16(acc[2 * nq],     aF, &bt[nq][0]);
            mma_bf16(acc[2 * nq + 1], aF, &bt[nq][2]);
        }
    }
}

// bias + relu + C-frag -> next-layer A-frag (bf16) for 4 kblocks (64 cols)
__device__ __forceinline__ void epi_build(const float (*acc)[4],
                                          const float* sB, int colBase,
                                          int l2x, uint32_t (*outA)[4]) {
    #pragma unroll
    for (int t = 0; t < 4; t++) {
        float b00 = sB[colBase + 16 * t + l2x];
        float b01 = sB[colBase + 16 * t + l2x + 1];
        float b10 = sB[colBase + 16 * t + 8 + l2x];
        float b11 = sB[colBase + 16 * t + 8 + l2x + 1];
        const float* cA = acc[2 * t];
        const float* cB = acc[2 * t + 1];
        outA[t][0] = packrelu(cA[0] + b00, cA[1] + b01);
        outA[t][1] = packrelu(cA[2] + b00, cA[3] + b01);
        outA[t][2] = packrelu(cB[0] + b10, cB[1] + b11);
        outA[t][3] = packrelu(cB[2] + b10, cB[3] + b11);
    }
}

// bias + relu + C-frag -> bf16 store into act buffer (64 cols per chunk)
__device__ __forceinline__ void epi_store(const float (*acc)[4],
                                          const float* sB, int colBase,
                                          __nv_bfloat16* act,
                                          int m0, int lane) {
    const int l2x = (lane & 3) * 2;
    const int row = m0 + (lane >> 2);
    #pragma unroll
    for (int t = 0; t < 8; t++) {
        int colL = colBase + t * 8 + l2x;
        float b0v = sB[colL], b1v = sB[colL + 1];
        __nv_bfloat162 v0 = __float22bfloat162_rn(make_float2(
            fmaxf(acc[t][0] + b0v, 0.0f), fmaxf(acc[t][1] + b1v, 0.0f)));
        __nv_bfloat162 v1 = __float22bfloat162_rn(make_float2(
            fmaxf(acc[t][2] + b0v, 0.0f), fmaxf(acc[t][3] + b1v, 0.0f)));
        *(__nv_bfloat162*)(act + row * SA + colL) = v0;
        *(__nv_bfloat162*)(act + (row + 8) * SA + colL) = v1;
    }
}

// --------------------------------- fused encode + MLP, 384 thr / 192 rows ---
__global__ void __launch_bounds__(THREADS, 1)
fused_all(const float* __restrict__ x,
          const float* __restrict__ table,
          const char* __restrict__ blob,
          const float* __restrict__ b1, const float* __restrict__ b2,
          const float* __restrict__ b3, const float* __restrict__ w4,
          const float* __restrict__ b4, float* __restrict__ out, int N) {
    extern __shared__ char smem[];
    const uint32_t sb = scvta(smem);
    __nv_bfloat16* sAct = (__nv_bfloat16*)(smem + ACT_OFF);
    __nv_bfloat16* sFeat = sAct;   // feat colocated; consumed before act writes
    float* sBias = (float*)(smem + BIAS_OFF);
    float* sW4   = (float*)(smem + W4_OFF);

    const int tid = threadIdx.x;
    const int lane = tid & 31;
    const int wid = tid >> 5;                // 0..11
    const int m0 = wid * 16;
    const int lr2 = lane & 15;
    const int lc2 = (lane >> 4) << 3;
    const int l2x = (lane & 3) * 2;
    const int rowBase = blockIdx.x * ROWS;

    // kick off W chunks 0,1 immediately (overlaps encode)
    issue_chunk(sb, blob, 0, tid);
    issue_chunk(sb, blob, 1, tid);

    // ---- biases + final weights ----
    for (int v = tid; v < 768; v += THREADS) {
        sBias[v] = (v < 256) ? b1[v] : (v < 512 ? b2[v - 256] : b3[v - 512]);
    }
    for (int v = tid; v < 771; v += THREADS) sW4[v] = (v < 768) ? w4[v] : b4[v - 768];

    // ---- encode: 2 threads per point, 8 levels each -> feat smem ----
    {
        const int p = tid >> 1;              // 0..191
        const int h = tid & 1;
        const int gp = min(rowBase + p, N - 1);
        float x0 = __ldg(x + 3 * gp + 0) * (1.0f / 1.5f);
        float x1 = __ldg(x + 3 * gp + 1) * (1.0f / 1.5f);
        float x2 = __ldg(x + 3 * gp + 2) * (1.0f / 1.5f);

        #pragma unroll
        for (int li = 0; li < 8; li++) {
            const int l = h * 8 + li;
            float s = c_scale[l];
            float px = x0 * s + 0.5f;
            float py = x1 * s + 0.5f;
            float pz = x2 * s + 0.5f;
            float fx = floorf(px), fy = floorf(py), fz = floorf(pz);
            float tx = px - fx, ty = py - fy, tz = pz - fz;
            uint32_t X = (uint32_t)fx, Y = (uint32_t)fy, Z = (uint32_t)fz;
            float wx[2] = {1.0f - tx, tx};
            float wy[2] = {1.0f - ty, ty};
            float wz[2] = {1.0f - tz, tz};

            float a0 = 0.0f, a1 = 0.0f;
            #pragma unroll
            for (int cc = 0; cc < 8; cc++) {
                uint32_t bx = (uint32_t)(cc & 1);
                uint32_t by = (uint32_t)((cc >> 1) & 1);
                uint32_t bz = (uint32_t)((cc >> 2) & 1);
                uint32_t cx = X + bx, cy = Y + by, cz = Z + bz;
                uint32_t idx;
                if (h == 0 && li < 5) {
                    uint32_t r1 = c_res1[li];
                    idx = cx + cy * r1 + cz * r1 * r1;   // dense
                } else {
                    idx = (cx * 1u ^ cy * 2654435761u ^ cz * 805459861u) & 524287u;
                }
                float w = wx[bx] * wy[by] * wz[bz];
                float2 t2 = __ldg((const float2*)table + (c_offset[l] + (int)idx));
                a0 += w * t2.x;
                a1 += w * t2.y;
            }
            *(__nv_bfloat162*)(sFeat + p * SF + 2 * l) =
                __float22bfloat162_rn(make_float2(a0, a1));
        }
    }
    __syncthreads();   // feat visible to all warps

    // A fragments for layer 1 (K=32 -> 2 kblocks); rows m0..m0+15
    uint32_t a1f[2][4];
    #pragma unroll
    for (int kb = 0; kb < 2; kb++)
        ldsm_x4(a1f[kb], sb + ACT_OFF
                + (uint32_t)(((m0 + lr2) * SF + kb * 16 + lc2) * 2));
    // feat fully consumed into a1f -> act region free for layer-2 output,
    // but only after ALL warps loaded a1f:
    __syncthreads();

    uint32_t a2f[16][4];
    float p0[3] = {0.0f, 0.0f, 0.0f};
    float p1[3] = {0.0f, 0.0f, 0.0f};

    // ================= LAYER 1 (K=32, chunks 0..3) -> a2f regs ===========
    #pragma unroll
    for (int c = 0; c < 4; c++) {
        const int s = c;
        if (c > 0) __syncthreads();   // all warps past chunk s-1
        issue_chunk(sb, blob, s + 2, tid);
        cp_wait<2>();                 // chunk s resident
        __syncthreads();
        uint32_t sW = sb + W_OFF + (uint32_t)(s % 3) * WSLOT;
        float acc[8][4];
        #pragma unroll
        for (int j = 0; j < 8; j++)
            #pragma unroll
            for (int q = 0; q < 4; q++) acc[j][q] = 0.0f;
        chunk_mma<2>(sW, lr2, lc2, a1f, acc);
        epi_build(acc, sBias, c * 64, l2x, &a2f[4 * c]);
    }

    // ================= LAYER 2 (K=256, chunks 4..7) -> act smem ==========
    #pragma unroll
    for (int c = 0; c < 4; c++) {
        const int s = 4 + c;
        __syncthreads();
        issue_chunk(sb, blob, s + 2, tid);
        cp_wait<2>();
        __syncthreads();
        uint32_t sW = sb + W_OFF + (uint32_t)(s % 3) * WSLOT;
        float acc[8][4];
        #pragma unroll
        for (int j = 0; j < 8; j++)
            #pragma unroll
            for (int q = 0; q < 4; q++) acc[j][q] = 0.0f;
        chunk_mma<16>(sW, lr2, lc2, a2f, acc);
        epi_store(acc, sBias + 256, c * 64, sAct, m0, lane);
    }

    // ================= LAYER 3 (K=256, chunks 8..11) + final =============
    #pragma unroll
    for (int c = 0; c < 4; c++) {
        const int s = 8 + c;
        __syncthreads();              // act writes / prior chunk reads done
        if (c < 2) issue_chunk(sb, blob, s + 2, tid);
        if (c < 2)      { cp_wait<2>(); }
        else if (c == 2){ cp_wait<1>(); }
        else            { cp_wait<0>(); }
        __syncthreads();
        uint32_t sW = sb + W_OFF + (uint32_t)(s % 3) * WSLOT;
        float acc[8][4];
        #pragma unroll
        for (int j = 0; j < 8; j++)
            #pragma unroll
            for (int q = 0; q < 4; q++) acc[j][q] = 0.0f;
        chunk_mma_smemA(sW, sb + ACT_OFF, m0, lr2, lc2, acc);
        // fused final layer: relu then dot with w4 columns (cols c*64..+63)
        const float* sB3 = sBias + 512;
        #pragma unroll
        for (int t = 0; t < 8; t++) {
            int col0 = c * 64 + t * 8 + l2x;
            float b0v = sB3[col0], b1v = sB3[col0 + 1];
            float v0 = fmaxf(acc[t][0] + b0v, 0.0f);
            float v1 = fmaxf(acc[t][1] + b1v, 0.0f);
            float v2 = fmaxf(acc[t][2] + b0v, 0.0f);
            float v3 = fmaxf(acc[t][3] + b1v, 0.0f);
            #pragma unroll
            for (int j = 0; j < 3; j++) {
                float w0 = sW4[col0 * 3 + j], w1v = sW4[(col0 + 1) * 3 + j];
                p0[j] += v0 * w0 + v1 * w1v;
                p1[j] += v2 * w0 + v3 * w1v;
            }
        }
    }

    // ---- quad reduce (lanes of one row differ in bits 0,1 of lane id) ----
    #pragma unroll
    for (int j = 0; j < 3; j++) {
        p0[j] += __shfl_xor_sync(0xFFFFFFFFu, p0[j], 1);
        p1[j] += __shfl_xor_sync(0xFFFFFFFFu, p1[j], 1);
        p0[j] += __shfl_xor_sync(0xFFFFFFFFu, p0[j], 2);
        p1[j] += __shfl_xor_sync(0xFFFFFFFFu, p1[j], 2);
    }
    if ((lane & 3) == 0) {
        int r0 = rowBase + m0 + (lane >> 2);
        int r1 = r0 + 8;
        if (r0 < N) {
            #pragma unroll
            for (int j = 0; j < 3; j++)
                out[3 * r0 + j] = 1.0f / (1.0f + expf(-(p0[j] + sW4[768 + j])));
        }
        if (r1 < N) {
            #pragma unroll
            for (int j = 0; j < 3; j++)
                out[3 * r1 + j] = 1.0f / (1.0f + expf(-(p1[j] + sW4[768 + j])));
        }
    }
}

// --------------------------------------------------------------- launcher ---
extern "C" void kernel_launch(void* const* d_in, const int* in_sizes, int n_in,
                              void* d_out, int out_size) {
    const float* x     = (const float*)d_in[0];
    const float* table = (const float*)d_in[1];
    const float* w1    = (const float*)d_in[2];
    const float* b1    = (const float*)d_in[3];
    const float* w2    = (const float*)d_in[4];
    const float* b2    = (const float*)d_in[5];
    const float* w3    = (const float*)d_in[6];
    const float* b3    = (const float*)d_in[7];
    const float* w4    = (const float*)d_in[8];
    const float* b4    = (const float*)d_in[9];
    float* out = (float*)d_out;

    int N = in_sizes[0] / 3;

    char* blob;
    cudaGetSymbolAddress((void**)&blob, g_wblob);

    cudaFuncSetAttribute(fused_all, cudaFuncAttributeMaxDynamicSharedMemorySize,
                         SMEM_BYTES);

    cvtw_kernel<<<256, 256>>>(w1, w2, w3, blob);
    fused_all<<<(N + ROWS - 1) / ROWS, THREADS, SMEM_BYTES>>>(
        x, table, blob, b1, b2, b3, w4, b4, out, N);
}

// round 13
// speedup vs baseline: 1.2600x; 1.2600x over previous
#include <cuda_runtime.h>
#include <cuda_bf16.h>
#include <cstdint>

// ---------------- hash-grid constants (precomputed from reference config) ----
__constant__ float c_scale[16] = {
    15.0f,          21.1106061f,   29.5549331f,   41.2242532f,
    57.3502375f,    79.6349472f,  110.4304720f,  152.9872000f,
    211.7969070f,  293.0667790f,  405.3746690f,  560.5743900f,
    775.0469010f, 1071.4291820f, 1481.0036600f, 2047.0f
};
__constant__ uint32_t c_res1[5] = {17u, 24u, 32u, 44u, 60u};
__constant__ int c_offset[16] = {
    0, 4920, 18744, 51512, 136696, 352696, 876984, 1401272,
    1925560, 2449848, 2974136, 3498424, 4022712, 4547000, 5071288, 5595576
};

// W chunk stream: 12 chunks (L1 c0..3, L2 c0..3, L3 c0..3), flat smem images
// (rows = K, 64 cols + 8 pad, stride 72 bf16 = 144 B).
__constant__ uint32_t c_chunk_off[12] = {
    0u, 4608u, 9216u, 13824u,
    18432u, 55296u, 92160u, 129024u,
    165888u, 202752u, 239616u, 276480u
};
__constant__ uint32_t c_chunk_bytes[12] = {
    4608u, 4608u, 4608u, 4608u,
    36864u, 36864u, 36864u, 36864u,
    36864u, 36864u, 36864u, 36864u
};

#define NPTS 524288
#define THREADS 128
#define ROWS 64

// pre-baked weight chunk blob (allocation-free rule: __device__ global)
__device__ char g_wblob[313344];

// ------------------------------------------------------- weight baking ------
__global__ void cvtw_kernel(const float* __restrict__ w1,
                            const float* __restrict__ w2,
                            const float* __restrict__ w3,
                            char* __restrict__ blob) {
    int i = blockIdx.x * 256 + threadIdx.x;   // i = k*256 + n, 65536 total
    int k = i >> 8, n = i & 255;
    uint32_t nc = (uint32_t)(n >> 6);
    uint32_t eoff = ((uint32_t)k * 72u + (uint32_t)(n & 63)) * 2u;
    *(__nv_bfloat16*)(blob + 18432u + nc * 36864u + eoff) = __float2bfloat16(w2[i]);
    *(__nv_bfloat16*)(blob + 165888u + nc * 36864u + eoff) = __float2bfloat16(w3[i]);
    if (k < 32)
        *(__nv_bfloat16*)(blob + nc * 4608u + eoff) = __float2bfloat16(w1[i]);
}

// ------------------------------------------------------------ PTX helpers ---
__device__ __forceinline__ uint32_t scvta(const void* p) {
    return (uint32_t)__cvta_generic_to_shared(p);
}
__device__ __forceinline__ void ldsm_x4(uint32_t* r, uint32_t addr) {
    asm volatile("ldmatrix.sync.aligned.m8n8.x4.shared.b16 {%0,%1,%2,%3}, [%4];"
                 : "=r"(r[0]), "=r"(r[1]), "=r"(r[2]), "=r"(r[3]) : "r"(addr));
}
__device__ __forceinline__ void ldsm_x4_t(uint32_t* r, uint32_t addr) {
    asm volatile("ldmatrix.sync.aligned.m8n8.x4.trans.shared.b16 {%0,%1,%2,%3}, [%4];"
                 : "=r"(r[0]), "=r"(r[1]), "=r"(r[2]), "=r"(r[3]) : "r"(addr));
}
__device__ __forceinline__ void mma_bf16(float* c, const uint32_t* a, const uint32_t* b) {
    asm volatile("mma.sync.aligned.m16n8k16.row.col.f32.bf16.bf16.f32 "
                 "{%0,%1,%2,%3}, {%4,%5,%6,%7}, {%8,%9}, {%0,%1,%2,%3};"
                 : "+f"(c[0]), "+f"(c[1]), "+f"(c[2]), "+f"(c[3])
                 : "r"(a[0]), "r"(a[1]), "r"(a[2]), "r"(a[3]),
                   "r"(b[0]), "r"(b[1]));
}
__device__ __forceinline__ void cp16(uint32_t smem, const void* gmem) {
    asm volatile("cp.async.cg.shared.global [%0], [%1], 16;"
                 :: "r"(smem), "l"(gmem));
}
__device__ __forceinline__ void cp_commit() {
    asm volatile("cp.async.commit_group;");
}
template <int NG>
__device__ __forceinline__ void cp_wait() {
    asm volatile("cp.async.wait_group %0;" :: "n"(NG));
}
__device__ __forceinline__ uint32_t packrelu(float a, float b) {
    __nv_bfloat162 t = __float22bfloat162_rn(
        make_float2(fmaxf(a, 0.0f), fmaxf(b, 0.0f)));
    return *(uint32_t*)&t;
}

// -------------------------------------------------------------- SMEM map ----
// 2-slot W ring, 85 KB total -> 2 CTAs per SM.
#define WSLOT     36864
#define W_OFF     0
#define FEAT_OFF  (2 * WSLOT)                 // 73728 : 64 x 40 bf16
#define SF        40
#define BIAS_OFF  (FEAT_OFF + ROWS * SF * 2)  // 78848 : float[768] b1|b2|b3
#define W4_OFF    (BIAS_OFF + 768 * 4)        // 81920 : float[772] w4|b4
#define SMEM_BYTES (W4_OFF + 772 * 4)         // 85008

// issue cp.async for chunk s into its ring slot (slot = s & 1)
__device__ __forceinline__ void issue_chunk(uint32_t sb, const char* blob,
                                            int s, int tid) {
    uint32_t dst = sb + W_OFF + (uint32_t)(s & 1) * WSLOT;
    uint32_t off = c_chunk_off[s];
    uint32_t bytes = c_chunk_bytes[s];
    for (uint32_t o = (uint32_t)tid * 16u; o < bytes; o += THREADS * 16u)
        cp16(dst + o, blob + off + o);
    cp_commit();
}

// MMA over one W chunk (64 cols), KB = K/16 kblocks. acc[8][4] += A*W.
template <int KB>
__device__ __forceinline__ void chunk_mma(uint32_t sW, int lr2, int lc2,
                                          const uint32_t (*aF)[4],
                                          float (*acc)[4]) {
    #pragma unroll
    for (int kb = 0; kb < KB; kb++) {
        uint32_t bt[4][4];
        #pragma unroll
        for (int nq = 0; nq < 4; nq++)
            ldsm_x4_t(bt[nq], sW + (uint32_t)(((kb * 16 + lr2) * 72
                                               + nq * 16 + lc2) * 2));
        #pragma unroll
        for (int nq = 0; nq < 4; nq++) {
            mma_bf16(acc[2 * nq],     aF[kb], &bt[nq][0]);
            mma_bf16(acc[2 * nq + 1], aF[kb], &bt[nq][2]);
        }
    }
}

// bias + relu + C-frag -> next-layer A-frag (bf16) for 4 kblocks (64 cols)
__device__ __forceinline__ void epi_build(const float (*acc)[4],
                                          const float* sB, int colBase,
                                          int l2x, uint32_t (*outA)[4]) {
    #pragma unroll
    for (int t = 0; t < 4; t++) {
        float b00 = sB[colBase + 16 * t + l2x];
        float b01 = sB[colBase + 16 * t + l2x + 1];
        float b10 = sB[colBase + 16 * t + 8 + l2x];
        float b11 = sB[colBase + 16 * t + 8 + l2x + 1];
        const float* cA = acc[2 * t];
        const float* cB = acc[2 * t + 1];
        outA[t][0] = packrelu(cA[0] + b00, cA[1] + b01);
        outA[t][1] = packrelu(cA[2] + b00, cA[3] + b01);
        outA[t][2] = packrelu(cB[0] + b10, cB[1] + b11);
        outA[t][3] = packrelu(cB[2] + b10, cB[3] + b11);
    }
}

// ------------------- fused encode + register-resident MLP, 2 CTAs per SM ----
__global__ void __launch_bounds__(THREADS, 2)
fused_all(const float* __restrict__ x,
          const float* __restrict__ table,
          const char* __restrict__ blob,
          const float* __restrict__ b1, const float* __restrict__ b2,
          const float* __restrict__ b3, const float* __restrict__ w4,
          const float* __restrict__ b4, float* __restrict__ out, int N) {
    extern __shared__ char smem[];
    const uint32_t sb = scvta(smem);
    __nv_bfloat16* sFeat = (__nv_bfloat16*)(smem + FEAT_OFF);
    float* sBias = (float*)(smem + BIAS_OFF);
    float* sW4   = (float*)(smem + W4_OFF);

    const int tid = threadIdx.x;
    const int lane = tid & 31;
    const int wid = tid >> 5;                // 0..3
    const int m0 = wid * 16;
    const int lr2 = lane & 15;
    const int lc2 = (lane >> 4) << 3;
    const int l2x = (lane & 3) * 2;
    const int rowBase = blockIdx.x * ROWS;

    // kick off W chunks 0,1 immediately (overlaps encode)
    issue_chunk(sb, blob, 0, tid);
    issue_chunk(sb, blob, 1, tid);

    // ---- biases + final weights ----
    #pragma unroll
    for (int v = tid; v < 768; v += THREADS)
        sBias[v] = (v < 256) ? b1[v] : (v < 512 ? b2[v - 256] : b3[v - 512]);
    for (int v = tid; v < 771; v += THREADS)
        sW4[v] = (v < 768) ? w4[v] : b4[v - 768];

    // ---- encode: 2 threads per point, 8 levels each -> feat smem ----
    {
        const int p = tid >> 1;              // 0..63
        const int h = tid & 1;
        const int gp = min(rowBase + p, N - 1);
        float x0 = __ldg(x + 3 * gp + 0) * (1.0f / 1.5f);
        float x1 = __ldg(x + 3 * gp + 1) * (1.0f / 1.5f);
        float x2 = __ldg(x + 3 * gp + 2) * (1.0f / 1.5f);

        #pragma unroll
        for (int li = 0; li < 8; li++) {
            const int l = h * 8 + li;
            float s = c_scale[l];
            float px = x0 * s + 0.5f;
            float py = x1 * s + 0.5f;
            float pz = x2 * s + 0.5f;
            float fx = floorf(px), fy = floorf(py), fz = floorf(pz);
            float tx = px - fx, ty = py - fy, tz = pz - fz;
            uint32_t X = (uint32_t)fx, Y = (uint32_t)fy, Z = (uint32_t)fz;
            float wx[2] = {1.0f - tx, tx};
            float wy[2] = {1.0f - ty, ty};
            float wz[2] = {1.0f - tz, tz};

            float a0 = 0.0f, a1 = 0.0f;
            #pragma unroll
            for (int cc = 0; cc < 8; cc++) {
                uint32_t bx = (uint32_t)(cc & 1);
                uint32_t by = (uint32_t)((cc >> 1) & 1);
                uint32_t bz = (uint32_t)((cc >> 2) & 1);
                uint32_t cx = X + bx, cy = Y + by, cz = Z + bz;
                uint32_t idx;
                if (h == 0 && li < 5) {
                    uint32_t r1 = c_res1[li];
                    idx = cx + cy * r1 + cz * r1 * r1;   // dense
                } else {
                    idx = (cx * 1u ^ cy * 2654435761u ^ cz * 805459861u) & 524287u;
                }
                float w = wx[bx] * wy[by] * wz[bz];
                float2 t2 = __ldg((const float2*)table + (c_offset[l] + (int)idx));
                a0 += w * t2.x;
                a1 += w * t2.y;
            }
            *(__nv_bfloat162*)(sFeat + p * SF + 2 * l) =
                __float22bfloat162_rn(make_float2(a0, a1));
        }
    }
    __syncthreads();   // feat visible to all warps

    // A fragments for layer 1 (K=32 -> 2 kblocks); rows m0..m0+15
    uint32_t a1f[2][4];
    #pragma unroll
    for (int kb = 0; kb < 2; kb++)
        ldsm_x4(a1f[kb], sb + FEAT_OFF
                + (uint32_t)(((m0 + lr2) * SF + kb * 16 + lc2) * 2));

    uint32_t a2f[16][4];
    uint32_t a3f[16][4];
    float p0[3] = {0.0f, 0.0f, 0.0f};
    float p1[3] = {0.0f, 0.0f, 0.0f};

    // ================= LAYER 1 (K=32, chunks s=0..3) =================
    #pragma unroll
    for (int c = 0; c < 4; c++) {
        const int s = c;
        cp_wait<1>();      // chunk s resident (one group still in flight)
        __syncthreads();
        uint32_t sW = sb + W_OFF + (uint32_t)(s & 1) * WSLOT;
        float acc[8][4];
        #pragma unroll
        for (int j = 0; j < 8; j++)
            #pragma unroll
            for (int q = 0; q < 4; q++) acc[j][q] = 0.0f;
        chunk_mma<2>(sW, lr2, lc2, a1f, acc);
        epi_build(acc, sBias, c * 64, l2x, &a2f[4 * c]);
        __syncthreads();   // all warps done reading slot (s&1)
        issue_chunk(sb, blob, s + 2, tid);
    }

    // ================= LAYER 2 (K=256, chunks s=4..7) =================
    #pragma unroll
    for (int c = 0; c < 4; c++) {
        const int s = 4 + c;
        cp_wait<1>();
        __syncthreads();
        uint32_t sW = sb + W_OFF + (uint32_t)(s & 1) * WSLOT;
        float acc[8][4];
        #pragma unroll
        for (int j = 0; j < 8; j++)
            #pragma unroll
            for (int q = 0; q < 4; q++) acc[j][q] = 0.0f;
        chunk_mma<16>(sW, lr2, lc2, a2f, acc);
        epi_build(acc, sBias + 256, c * 64, l2x, &a3f[4 * c]);
        __syncthreads();
        issue_chunk(sb, blob, s + 2, tid);
    }

    // ================= LAYER 3 (K=256, chunks s=8..11) + final ==========
    #pragma unroll
    for (int c = 0; c < 4; c++) {
        if (c < 3) { cp_wait<1>(); } else { cp_wait<0>(); }
        __syncthreads();
        const int s = 8 + c;
        uint32_t sW = sb + W_OFF + (uint32_t)(s & 1) * WSLOT;
        float acc[8][4];
        #pragma unroll
        for (int j = 0; j < 8; j++)
            #pragma unroll
            for (int q = 0; q < 4; q++) acc[j][q] = 0.0f;
        chunk_mma<16>(sW, lr2, lc2, a3f, acc);
        if (c < 2) {
            __syncthreads();   // done reading slot before next issue overwrites
            issue_chunk(sb, blob, s + 2, tid);
        }
        // fused final layer: relu then dot with w4 columns (cols c*64..+63)
        const float* sB3 = sBias + 512;
        #pragma unroll
        for (int t = 0; t < 8; t++) {
            int col0 = c * 64 + t * 8 + l2x;
            float b0v = sB3[col0], b1v = sB3[col0 + 1];
            float v0 = fmaxf(acc[t][0] + b0v, 0.0f);
            float v1 = fmaxf(acc[t][1] + b1v, 0.0f);
            float v2 = fmaxf(acc[t][2] + b0v, 0.0f);
            float v3 = fmaxf(acc[t][3] + b1v, 0.0f);
            #pragma unroll
            for (int j = 0; j < 3; j++) {
                float w0 = sW4[col0 * 3 + j], w1v = sW4[(col0 + 1) * 3 + j];
                p0[j] += v0 * w0 + v1 * w1v;
                p1[j] += v2 * w0 + v3 * w1v;
            }
        }
    }

    // ---- quad reduce (lanes of one row differ in bits 0,1 of lane id) ----
    #pragma unroll
    for (int j = 0; j < 3; j++) {
        p0[j] += __shfl_xor_sync(0xFFFFFFFFu, p0[j], 1);
        p1[j] += __shfl_xor_sync(0xFFFFFFFFu, p1[j], 1);
        p0[j] += __shfl_xor_sync(0xFFFFFFFFu, p0[j], 2);
        p1[j] += __shfl_xor_sync(0xFFFFFFFFu, p1[j], 2);
    }
    if ((lane & 3) == 0) {
        int r0 = rowBase + m0 + (lane >> 2);
        int r1 = r0 + 8;
        if (r0 < N) {
            #pragma unroll
            for (int j = 0; j < 3; j++)
                out[3 * r0 + j] = 1.0f / (1.0f + expf(-(p0[j] + sW4[768 + j])));
        }
        if (r1 < N) {
            #pragma unroll
            for (int j = 0; j < 3; j++)
                out[3 * r1 + j] = 1.0f / (1.0f + expf(-(p1[j] + sW4[768 + j])));
        }
    }
}

// --------------------------------------------------------------- launcher ---
extern "C" void kernel_launch(void* const* d_in, const int* in_sizes, int n_in,
                              void* d_out, int out_size) {
    const float* x     = (const float*)d_in[0];
    const float* table = (const float*)d_in[1];
    const float* w1    = (const float*)d_in[2];
    const float* b1    = (const float*)d_in[3];
    const float* w2    = (const float*)d_in[4];
    const float* b2    = (const float*)d_in[5];
    const float* w3    = (const float*)d_in[6];
    const float* b3    = (const float*)d_in[7];
    const float* w4    = (const float*)d_in[8];
    const float* b4    = (const float*)d_in[9];
    float* out = (float*)d_out;

    int N = in_sizes[0] / 3;

    char* blob;
    cudaGetSymbolAddress((void**)&blob, g_wblob);

    cudaFuncSetAttribute(fused_all, cudaFuncAttributeMaxDynamicSharedMemorySize,
                         SMEM_BYTES);

    cvtw_kernel<<<256, 256>>>(w1, w2, w3, blob);
    fused_all<<<(N + ROWS - 1) / ROWS, THREADS, SMEM_BYTES>>>(
        x, table, blob, b1, b2, b3, w4, b4, out, N);
}

// round 14
// speedup vs baseline: 1.3874x; 1.1012x over previous
#include <cuda_runtime.h>
#include <cuda_bf16.h>
#include <cstdint>

// ---------------- hash-grid constants (precomputed from reference config) ----
__constant__ float c_scale[16] = {
    15.0f,          21.1106061f,   29.5549331f,   41.2242532f,
    57.3502375f,    79.6349472f,  110.4304720f,  152.9872000f,
    211.7969070f,  293.0667790f,  405.3746690f,  560.5743900f,
    775.0469010f, 1071.4291820f, 1481.0036600f, 2047.0f
};
__constant__ uint32_t c_res1[5] = {17u, 24u, 32u, 44u, 60u};
__constant__ int c_offset[16] = {
    0, 4920, 18744, 51512, 136696, 352696, 876984, 1401272,
    1925560, 2449848, 2974136, 3498424, 4022712, 4547000, 5071288, 5595576
};

// W chunk stream: 12 chunks (L1 c0..3, L2 c0..3, L3 c0..3), flat smem images
// (rows = K, 64 cols + 8 pad, stride 72 bf16 = 144 B).
__constant__ uint32_t c_chunk_off[12] = {
    0u, 4608u, 9216u, 13824u,
    18432u, 55296u, 92160u, 129024u,
    165888u, 202752u, 239616u, 276480u
};
__constant__ uint32_t c_chunk_bytes[12] = {
    4608u, 4608u, 4608u, 4608u,
    36864u, 36864u, 36864u, 36864u,
    36864u, 36864u, 36864u, 36864u
};

#define NPTS 524288
#define THREADS 256
#define ROWS 128

// pre-baked weight chunk blob (allocation-free rule: __device__ global)
__device__ char g_wblob[313344];

// ------------------------------------------------------- weight baking ------
__global__ void cvtw_kernel(const float* __restrict__ w1,
                            const float* __restrict__ w2,
                            const float* __restrict__ w3,
                            char* __restrict__ blob) {
    int i = blockIdx.x * 256 + threadIdx.x;   // i = k*256 + n, 65536 total
    int k = i >> 8, n = i & 255;
    uint32_t nc = (uint32_t)(n >> 6);
    uint32_t eoff = ((uint32_t)k * 72u + (uint32_t)(n & 63)) * 2u;
    *(__nv_bfloat16*)(blob + 18432u + nc * 36864u + eoff) = __float2bfloat16(w2[i]);
    *(__nv_bfloat16*)(blob + 165888u + nc * 36864u + eoff) = __float2bfloat16(w3[i]);
    if (k < 32)
        *(__nv_bfloat16*)(blob + nc * 4608u + eoff) = __float2bfloat16(w1[i]);
}

// ------------------------------------------------------------ PTX helpers ---
__device__ __forceinline__ uint32_t scvta(const void* p) {
    return (uint32_t)__cvta_generic_to_shared(p);
}
__device__ __forceinline__ void ldsm_x4(uint32_t* r, uint32_t addr) {
    asm volatile("ldmatrix.sync.aligned.m8n8.x4.shared.b16 {%0,%1,%2,%3}, [%4];"
                 : "=r"(r[0]), "=r"(r[1]), "=r"(r[2]), "=r"(r[3]) : "r"(addr));
}
__device__ __forceinline__ void ldsm_x4_t(uint32_t* r, uint32_t addr) {
    asm volatile("ldmatrix.sync.aligned.m8n8.x4.trans.shared.b16 {%0,%1,%2,%3}, [%4];"
                 : "=r"(r[0]), "=r"(r[1]), "=r"(r[2]), "=r"(r[3]) : "r"(addr));
}
__device__ __forceinline__ void mma_bf16(float* c, const uint32_t* a, const uint32_t* b) {
    asm volatile("mma.sync.aligned.m16n8k16.row.col.f32.bf16.bf16.f32 "
                 "{%0,%1,%2,%3}, {%4,%5,%6,%7}, {%8,%9}, {%0,%1,%2,%3};"
                 : "+f"(c[0]), "+f"(c[1]), "+f"(c[2]), "+f"(c[3])
                 : "r"(a[0]), "r"(a[1]), "r"(a[2]), "r"(a[3]),
                   "r"(b[0]), "r"(b[1]));
}
__device__ __forceinline__ void cp16(uint32_t smem, const void* gmem) {
    asm volatile("cp.async.cg.shared.global [%0], [%1], 16;"
                 :: "r"(smem), "l"(gmem));
}
__device__ __forceinline__ void cp_commit() {
    asm volatile("cp.async.commit_group;");
}
template <int NG>
__device__ __forceinline__ void cp_wait() {
    asm volatile("cp.async.wait_group %0;" :: "n"(NG));
}
__device__ __forceinline__ uint32_t packrelu(float a, float b) {
    __nv_bfloat162 t = __float22bfloat162_rn(
        make_float2(fmaxf(a, 0.0f), fmaxf(b, 0.0f)));
    return *(uint32_t*)&t;
}

// -------------------------------------------------------------- SMEM map ----
#define WSLOT     36864
#define W_OFF     0
#define FEAT_OFF  (2 * WSLOT)                 // 73728 : 128 x 40 bf16
#define SF        40
#define BIAS_OFF  (FEAT_OFF + ROWS * SF * 2)  // 83968 : float[768] b1|b2|b3
#define W4_OFF    (BIAS_OFF + 768 * 4)        // 87040 : float[772] w4|b4
#define SMEM_BYTES (W4_OFF + 772 * 4)         // 90128

// issue cp.async for chunk s into its ring slot (slot = s & 1)
__device__ __forceinline__ void issue_chunk(uint32_t sb, const char* blob,
                                            int s, int tid) {
    uint32_t dst = sb + W_OFF + (uint32_t)(s & 1) * WSLOT;
    uint32_t off = c_chunk_off[s];
    uint32_t bytes = c_chunk_bytes[s];
    for (uint32_t o = (uint32_t)tid * 16u, step = THREADS * 16u; o < bytes; o += step)
        cp16(dst + o, blob + off + o);
    cp_commit();
}

// load kblock kb's B fragments (16 k-rows x 64 cols) from smem chunk
// addr = wBase + kb*2304 + nq*32   (2304 = 16 rows * 144 B; 32 = 16 cols * 2)
__device__ __forceinline__ void load_bt(uint32_t wBase, int kb, uint32_t (*bt)[4]) {
    uint32_t a = wBase + (uint32_t)kb * 2304u;
    ldsm_x4_t(bt[0], a);
    ldsm_x4_t(bt[1], a + 32u);
    ldsm_x4_t(bt[2], a + 64u);
    ldsm_x4_t(bt[3], a + 96u);
}
__device__ __forceinline__ void mma_bt(float (*acc)[4], const uint32_t* aF,
                                       const uint32_t (*bt)[4]) {
    #pragma unroll
    for (int nq = 0; nq < 4; nq++) {
        mma_bf16(acc[2 * nq],     aF, &bt[nq][0]);
        mma_bf16(acc[2 * nq + 1], aF, &bt[nq][2]);
    }
}

// MMA over one W chunk (64 cols), KB kblocks, B-fragment double buffered so
// kblock k+1's ldsm overlaps kblock k's 8 MMAs.
template <int KB>
__device__ __forceinline__ void chunk_mma(uint32_t wBase,
                                          const uint32_t (*aF)[4],
                                          float (*acc)[4]) {
    uint32_t bt0[4][4], bt1[4][4];
    load_bt(wBase, 0, bt0);
    #pragma unroll
    for (int kb = 0; kb < KB; kb++) {
        if (kb & 1) {
            if (kb + 1 < KB) load_bt(wBase, kb + 1, bt0);
            mma_bt(acc, aF[kb], bt1);
        } else {
            if (kb + 1 < KB) load_bt(wBase, kb + 1, bt1);
            mma_bt(acc, aF[kb], bt0);
        }
    }
}

// bias + relu + C-frag -> next-layer A-frag (bf16) for 4 kblocks (64 cols)
__device__ __forceinline__ void epi_build(const float (*acc)[4],
                                          const float* sB, int colBase,
                                          int l2x, uint32_t (*outA)[4]) {
    #pragma unroll
    for (int t = 0; t < 4; t++) {
        float b00 = sB[colBase + 16 * t + l2x];
        float b01 = sB[colBase + 16 * t + l2x + 1];
        float b10 = sB[colBase + 16 * t + 8 + l2x];
        float b11 = sB[colBase + 16 * t + 8 + l2x + 1];
        const float* cA = acc[2 * t];
        const float* cB = acc[2 * t + 1];
        outA[t][0] = packrelu(cA[0] + b00, cA[1] + b01);
        outA[t][1] = packrelu(cA[2] + b00, cA[3] + b01);
        outA[t][2] = packrelu(cB[0] + b10, cB[1] + b11);
        outA[t][3] = packrelu(cB[2] + b10, cB[3] + b11);
    }
}

// --------------------------------- fused encode + register-resident MLP -----
__global__ void __launch_bounds__(THREADS)
fused_all(const float* __restrict__ x,
          const float* __restrict__ table,
          const char* __restrict__ blob,
          const float* __restrict__ b1, const float* __restrict__ b2,
          const float* __restrict__ b3, const float* __restrict__ w4,
          const float* __restrict__ b4, float* __restrict__ out, int N) {
    extern __shared__ char smem[];
    const uint32_t sb = scvta(smem);
    __nv_bfloat16* sFeat = (__nv_bfloat16*)(smem + FEAT_OFF);
    float* sBias = (float*)(smem + BIAS_OFF);
    float* sW4   = (float*)(smem + W4_OFF);

    const int tid = threadIdx.x;
    const int lane = tid & 31;
    const int wid = tid >> 5;                // 0..7
    const int m0 = wid * 16;
    const int lr2 = lane & 15;
    const int lc2 = (lane >> 4) << 3;
    const int l2x = (lane & 3) * 2;
    const int rowBase = blockIdx.x * ROWS;
    // per-warp ldsm base offset inside a W slot: (lr2*72 + lc2)*2
    const uint32_t wWarpOff = (uint32_t)((lr2 * 72 + lc2) * 2);

    // kick off W chunks 0,1 immediately (overlaps encode)
    issue_chunk(sb, blob, 0, tid);
    issue_chunk(sb, blob, 1, tid);

    // ---- biases + final weights ----
    sBias[tid]       = b1[tid];
    sBias[256 + tid] = b2[tid];
    sBias[512 + tid] = b3[tid];
    for (int v = tid; v < 771; v += THREADS)
        sW4[v] = (v < 768) ? w4[v] : b4[v - 768];

    // ---- encode: 2 threads per point, 8 levels each -> feat smem ----
    {
        const int p = tid >> 1;
        const int h = tid & 1;
        const int gp = min(rowBase + p, N - 1);
        float x0 = __ldg(x + 3 * gp + 0) * (1.0f / 1.5f);
        float x1 = __ldg(x + 3 * gp + 1) * (1.0f / 1.5f);
        float x2 = __ldg(x + 3 * gp + 2) * (1.0f / 1.5f);

        #pragma unroll
        for (int li = 0; li < 8; li++) {
            const int l = h * 8 + li;
            float s = c_scale[l];
            float px = x0 * s + 0.5f;
            float py = x1 * s + 0.5f;
            float pz = x2 * s + 0.5f;
            float fx = floorf(px), fy = floorf(py), fz = floorf(pz);
            float tx = px - fx, ty = py - fy, tz = pz - fz;
            uint32_t X = (uint32_t)fx, Y = (uint32_t)fy, Z = (uint32_t)fz;
            float wx[2] = {1.0f - tx, tx};
            float wy[2] = {1.0f - ty, ty};
            float wz[2] = {1.0f - tz, tz};

            float a0 = 0.0f, a1 = 0.0f;
            #pragma unroll
            for (int cc = 0; cc < 8; cc++) {
                uint32_t bx = (uint32_t)(cc & 1);
                uint32_t by = (uint32_t)((cc >> 1) & 1);
                uint32_t bz = (uint32_t)((cc >> 2) & 1);
                uint32_t cx = X + bx, cy = Y + by, cz = Z + bz;
                uint32_t idx;
                if (h == 0 && li < 5) {
                    uint32_t r1 = c_res1[li];
                    idx = cx + cy * r1 + cz * r1 * r1;   // dense
                } else {
                    idx = (cx * 1u ^ cy * 2654435761u ^ cz * 805459861u) & 524287u;
                }
                float w = wx[bx] * wy[by] * wz[bz];
                float2 t2 = __ldg((const float2*)table + (c_offset[l] + (int)idx));
                a0 += w * t2.x;
                a1 += w * t2.y;
            }
            *(__nv_bfloat162*)(sFeat + p * SF + 2 * l) =
                __float22bfloat162_rn(make_float2(a0, a1));
        }
    }
    __syncthreads();   // feat visible to all warps

    // A fragments for layer 1 (K=32 -> 2 kblocks); rows m0..m0+15
    uint32_t a1f[2][4];
    #pragma unroll
    for (int kb = 0; kb < 2; kb++)
        ldsm_x4(a1f[kb], sb + FEAT_OFF
                + (uint32_t)(((m0 + lr2) * SF + kb * 16 + lc2) * 2));

    uint32_t a2f[16][4];
    uint32_t a3f[16][4];
    float p0[3] = {0.0f, 0.0f, 0.0f};
    float p1[3] = {0.0f, 0.0f, 0.0f};

    // ================= LAYER 1 (K=32, chunks s=0..3) =================
    #pragma unroll
    for (int c = 0; c < 4; c++) {
        const int s = c;
        cp_wait<1>();      // chunk s resident (one group still in flight)
        __syncthreads();
        uint32_t wBase = sb + W_OFF + (uint32_t)(s & 1) * WSLOT + wWarpOff;
        float acc[8][4];
        #pragma unroll
        for (int j = 0; j < 8; j++)
            #pragma unroll
            for (int q = 0; q < 4; q++) acc[j][q] = 0.0f;
        chunk_mma<2>(wBase, a1f, acc);
        epi_build(acc, sBias, c * 64, l2x, &a2f[4 * c]);
        __syncthreads();   // all warps done reading slot (s&1)
        issue_chunk(sb, blob, s + 2, tid);
    }

    // ================= LAYER 2 (K=256, chunks s=4..7) =================
    #pragma unroll
    for (int c = 0; c < 4; c++) {
        const int s = 4 + c;
        cp_wait<1>();
        __syncthreads();
        uint32_t wBase = sb + W_OFF + (uint32_t)(s & 1) * WSLOT + wWarpOff;
        float acc[8][4];
        #pragma unroll
        for (int j = 0; j < 8; j++)
            #pragma unroll
            for (int q = 0; q < 4; q++) acc[j][q] = 0.0f;
        chunk_mma<16>(wBase, a2f, acc);
        epi_build(acc, sBias + 256, c * 64, l2x, &a3f[4 * c]);
        __syncthreads();
        issue_chunk(sb, blob, s + 2, tid);
    }

    // ================= LAYER 3 (K=256, chunks s=8..11) + final ==========
    #pragma unroll
    for (int c = 0; c < 4; c++) {
        if (c < 3) { cp_wait<1>(); } else { cp_wait<0>(); }
        __syncthreads();
        const int s = 8 + c;
        uint32_t wBase = sb + W_OFF + (uint32_t)(s & 1) * WSLOT + wWarpOff;
        float acc[8][4];
        #pragma unroll
        for (int j = 0; j < 8; j++)
            #pragma unroll
            for (int q = 0; q < 4; q++) acc[j][q] = 0.0f;
        chunk_mma<16>(wBase, a3f, acc);
        if (c < 2) {
            __syncthreads();   // done reading slot before next issue overwrites
            issue_chunk(sb, blob, s + 2, tid);
        }
        // fused final layer: relu then dot with w4 columns (cols c*64..+63)
        const float* sB3 = sBias + 512;
        #pragma unroll
        for (int t = 0; t < 8; t++) {
            int col0 = c * 64 + t * 8 + l2x;
            float b0v = sB3[col0], b1v = sB3[col0 + 1];
            float v0 = fmaxf(acc[t][0] + b0v, 0.0f);
            float v1 = fmaxf(acc[t][1] + b1v, 0.0f);
            float v2 = fmaxf(acc[t][2] + b0v, 0.0f);
            float v3 = fmaxf(acc[t][3] + b1v, 0.0f);
            #pragma unroll
            for (int j = 0; j < 3; j++) {
                float w0 = sW4[col0 * 3 + j], w1v = sW4[(col0 + 1) * 3 + j];
                p0[j] += v0 * w0 + v1 * w1v;
                p1[j] += v2 * w0 + v3 * w1v;
            }
        }
    }

    // ---- quad reduce (lanes of one row differ in bits 0,1 of lane id) ----
    #pragma unroll
    for (int j = 0; j < 3; j++) {
        p0[j] += __shfl_xor_sync(0xFFFFFFFFu, p0[j], 1);
        p1[j] += __shfl_xor_sync(0xFFFFFFFFu, p1[j], 1);
        p0[j] += __shfl_xor_sync(0xFFFFFFFFu, p0[j], 2);
        p1[j] += __shfl_xor_sync(0xFFFFFFFFu, p1[j], 2);
    }
    if ((lane & 3) == 0) {
        int r0 = rowBase + m0 + (lane >> 2);
        int r1 = r0 + 8;
        if (r0 < N) {
            #pragma unroll
            for (int j = 0; j < 3; j++)
                out[3 * r0 + j] = 1.0f / (1.0f + expf(-(p0[j] + sW4[768 + j])));
        }
        if (r1 < N) {
            #pragma unroll
            for (int j = 0; j < 3; j++)
                out[3 * r1 + j] = 1.0f / (1.0f + expf(-(p1[j] + sW4[768 + j])));
        }
    }
}

// --------------------------------------------------------------- launcher ---
extern "C" void kernel_launch(void* const* d_in, const int* in_sizes, int n_in,
                              void* d_out, int out_size) {
    const float* x     = (const float*)d_in[0];
    const float* table = (const float*)d_in[1];
    const float* w1    = (const float*)d_in[2];
    const float* b1    = (const float*)d_in[3];
    const float* w2    = (const float*)d_in[4];
    const float* b2    = (const float*)d_in[5];
    const float* w3    = (const float*)d_in[6];
    const float* b3    = (const float*)d_in[7];
    const float* w4    = (const float*)d_in[8];
    const float* b4    = (const float*)d_in[9];
    float* out = (float*)d_out;

    int N = in_sizes[0] / 3;

    char* blob;
    cudaGetSymbolAddress((void**)&blob, g_wblob);

    cudaFuncSetAttribute(fused_all, cudaFuncAttributeMaxDynamicSharedMemorySize,
                         SMEM_BYTES);

    cvtw_kernel<<<256, 256>>>(w1, w2, w3, blob);
    fused_all<<<(N + ROWS - 1) / ROWS, THREADS, SMEM_BYTES>>>(
        x, table, blob, b1, b2, b3, w4, b4, out, N);
}